// round 7
// baseline (speedup 1.0000x reference)
#include <cuda_runtime.h>
#include <math.h>

#define Dm 1024
#define Hm 4096
#define Lm 12
#define Vm 50277
#define NB 148
#define NT 1024
#define NWG (NB * 32)            // total warps in grid
#define NTH (NB * NT)            // total threads in grid

// ---------------- global scratch (allocation-free) ----------------
__device__ float g_k[Dm], g_v[Dm], g_r[Dm];
__device__ float g_po[4 * Dm];
__device__ float g_fk[Hm], g_fr[Dm];
__device__ float g_pf[4 * Dm];

// ---------------- distributed-flag grid barrier ----------------
// Each block owns a 128B-padded flag; arrival = parallel release-stores to
// distinct L2 lines (no same-address atomic serialization). Block 0 detects
// (148 parallel acquire polls) and publishes g_gen2. Monotonic => replay-safe.
__device__ unsigned g_flag[NB * 32];   // stride 32 u32 = 128B per block
__device__ unsigned g_gen2;

__device__ __forceinline__ unsigned ld_acq(const unsigned* p) {
    unsigned v;
    asm volatile("ld.acquire.gpu.global.u32 %0, [%1];" : "=r"(v) : "l"(p) : "memory");
    return v;
}
__device__ __forceinline__ void st_rel(unsigned* p, unsigned v) {
    asm volatile("st.release.gpu.global.u32 [%0], %1;" :: "l"(p), "r"(v) : "memory");
}

// target strictly increases across phases AND across graph replays
__device__ __forceinline__ void gsync(unsigned target) {
    __syncthreads();
    if (threadIdx.x == 0) st_rel(&g_flag[blockIdx.x * 32], target);
    if (blockIdx.x == 0) {
        if (threadIdx.x < NB) {
            while ((int)(ld_acq(&g_flag[threadIdx.x * 32]) - target) < 0) { }
        }
        __syncthreads();
        if (threadIdx.x == 0) st_rel(&g_gen2, target);
        __syncthreads();
    } else {
        if (threadIdx.x == 0) {
            while ((int)(ld_acq(&g_gen2) - target) < 0) { }
        }
        __syncthreads();
    }
}

// ---------------- fire-and-forget L2 prefetch ----------------
__device__ __forceinline__ void pf_l2(const void* p, size_t bytes) {
    const char* c = (const char*)p;
    size_t start = ((size_t)(blockIdx.x * NT + threadIdx.x)) << 7;
    size_t step  = ((size_t)NTH) << 7;
    for (size_t i = start; i < bytes; i += step)
        asm volatile("prefetch.global.L2 [%0];" :: "l"(c + i));
}

// ---------------- reductions ----------------
__device__ __forceinline__ float warp_sum(float v) {
#pragma unroll
    for (int o = 16; o; o >>= 1) v += __shfl_down_sync(0xffffffffu, v, o);
    return v;
}

__device__ __forceinline__ float block_sum(float v, float* sbuf) {
    int lane = threadIdx.x & 31, wid = threadIdx.x >> 5;
    v = warp_sum(v);
    __syncthreads();
    if (lane == 0) sbuf[wid] = v;
    __syncthreads();
    if (wid == 0) {
        float t = sbuf[lane];
        t = warp_sum(t);
        if (lane == 0) sbuf[0] = t;
    }
    __syncthreads();
    return sbuf[0];
}

__device__ __forceinline__ float ln1024(float v, const float* __restrict__ w,
                                        const float* __restrict__ b, float* sbuf) {
    float mu = block_sum(v, sbuf) * (1.0f / Dm);
    float d = v - mu;
    float var = block_sum(d * d, sbuf) * (1.0f / Dm);
    return d * rsqrtf(var + 1e-5f) * w[threadIdx.x] + b[threadIdx.x];
}

// ---------------- dot helpers ----------------
__device__ __forceinline__ float dot8(const float4* __restrict__ w,
                                      const float4* __restrict__ x, int lane) {
    float acc = 0.f;
#pragma unroll
    for (int j = 0; j < 8; j++) {
        float4 a = __ldcs(w + j * 32 + lane);
        float4 c = x[j * 32 + lane];
        acc = fmaf(a.x, c.x, fmaf(a.y, c.y, fmaf(a.z, c.z, fmaf(a.w, c.w, acc))));
    }
    return warp_sum(acc);
}

__device__ __forceinline__ float dot2(const float4* __restrict__ w,
                                      const float4* __restrict__ x, int lane) {
    float acc = 0.f;
#pragma unroll
    for (int j = 0; j < 2; j++) {
        float4 a = __ldcs(w + j * 32 + lane);
        float4 c = x[j * 32 + lane];
        acc = fmaf(a.x, c.x, fmaf(a.y, c.y, fmaf(a.z, c.z, fmaf(a.w, c.w, acc))));
    }
    return warp_sum(acc);
}

// ---------------- the whole network in one persistent kernel ----------------
__global__ __launch_bounds__(NT, 1) void rwkv_all(
    const int* __restrict__ tok, const float* __restrict__ state,
    const float* __restrict__ emb,
    const float* __restrict__ ln0w, const float* __restrict__ ln0b,
    const float* __restrict__ ln1w, const float* __restrict__ ln1b,
    const float* __restrict__ tmk, const float* __restrict__ tmv,
    const float* __restrict__ tmr, const float* __restrict__ tf,
    const float* __restrict__ td,
    const float* __restrict__ kw, const float* __restrict__ vw,
    const float* __restrict__ rw, const float* __restrict__ ow,
    const float* __restrict__ ln2w, const float* __restrict__ ln2b,
    const float* __restrict__ fmk, const float* __restrict__ fmr,
    const float* __restrict__ fkw, const float* __restrict__ fvw,
    const float* __restrict__ frw,
    const float* __restrict__ lnoutw, const float* __restrict__ lnoutb,
    const float* __restrict__ headw,
    float* __restrict__ logits, float* __restrict__ ns)
{
    __shared__ float s_v0[Dm], s_v1[Dm], s_v2[Dm];
    __shared__ float s_fk[Hm];
    __shared__ float s_red[32];
    __shared__ unsigned s_base;

    const int tid = threadIdx.x;
    const int wid = tid >> 5, lane = tid & 31;
    const int gw = blockIdx.x * 32 + wid;
    const bool b0 = (blockIdx.x == 0);

    const size_t DD = (size_t)Dm * Dm * sizeof(float);   // 4MB
    const size_t HD = (size_t)Hm * Dm * sizeof(float);   // 16MB

    // snapshot generation (stable between replays; all flags == g_gen2 here)
    if (tid == 0) s_base = ld_acq(&g_gen2);

    // ---- warm L2 with layer-0 phase-1 weights (non-blocking hints) ----
    pf_l2(kw, DD); pf_l2(vw, DD); pf_l2(rw, DD);

    // ---- embed + ln0 (redundant per block; x lives in a register) ----
    float x = ln1024(emb[(size_t)(*tok) * Dm + tid], ln0w, ln0b, s_red);
    unsigned bar = s_base;     // s_base valid: ln1024 did __syncthreads

    for (int l = 0; l < Lm; l++) {
        const float* s = state + (size_t)l * 5 * Dm;
        float* nsl = ns + (size_t)l * 5 * Dm;
        const size_t dd = (size_t)l * Dm * Dm;
        const size_t hd = (size_t)l * Hm * Dm;

        // ---- phase 1: LN1 + token-mix, then k/v/r matvec ----
        {
            float xx = ln1024(x, ln1w + l * Dm, ln1b + l * Dm, s_red);
            float ss = s[1 * Dm + tid];
            float mk = tmk[l * Dm + tid], mv = tmv[l * Dm + tid], mr = tmr[l * Dm + tid];
            s_v0[tid] = xx * mk + ss * (1.0f - mk);
            s_v1[tid] = xx * mv + ss * (1.0f - mv);
            s_v2[tid] = xx * mr + ss * (1.0f - mr);
            if (b0) nsl[1 * Dm + tid] = xx;
        }
        __syncthreads();
        for (int t = gw; t < 3 * Dm; t += NWG) {
            int mat = t >> 10, row = t & (Dm - 1);
            const float* W = (mat == 0) ? (kw + dd) : (mat == 1) ? (vw + dd) : (rw + dd);
            const float* xv = (mat == 0) ? s_v0 : (mat == 1) ? s_v1 : s_v2;
            float acc = dot8((const float4*)(W + (size_t)row * Dm), (const float4*)xv, lane);
            if (lane == 0) {
                if (mat == 0)      __stcg(&g_k[row], acc);
                else if (mat == 1) __stcg(&g_v[row], acc);
                else               __stcg(&g_r[row], 1.0f / (1.0f + expf(-acc)));
            }
        }
        pf_l2(ow + dd, DD);
        gsync(++bar);

        // ---- phase 2: WKV recurrence (redundant) + ow partials ----
        {
            float k = __ldcg(&g_k[tid]), v = __ldcg(&g_v[tid]);
            float aa = s[2 * Dm + tid], bb = s[3 * Dm + tid], pp = s[4 * Dm + tid];
            float ww = tf[l * Dm + tid] + k;
            float p = fmaxf(pp, ww);
            float e1 = expf(pp - p), e2 = expf(ww - p);
            float wkv = (e1 * aa + e2 * v) / (e1 * bb + e2);
            float ww2 = pp + td[l * Dm + tid];
            float p2 = fmaxf(ww2, k);
            float f1 = expf(ww2 - p2), f2 = expf(k - p2);
            s_v0[tid] = __ldcg(&g_r[tid]) * wkv;
            if (b0) {
                nsl[2 * Dm + tid] = f1 * aa + f2 * v;
                nsl[3 * Dm + tid] = f1 * bb + f2;
                nsl[4 * Dm + tid] = p2;
            }
        }
        __syncthreads();
        for (int t = gw; t < 4 * Dm; t += NWG) {
            int row = t >> 2, ch = t & 3;
            float acc = dot2((const float4*)(ow + dd + (size_t)row * Dm + ch * 256),
                             (const float4*)(s_v0 + ch * 256), lane);
            if (lane == 0) __stcg(&g_po[ch * Dm + row], acc);
        }
        pf_l2(fkw + hd, HD); pf_l2(frw + dd, DD);
        gsync(++bar);

        // ---- phase 3: residual + LN2 + FFN mix, then fk/fr matvec ----
        x = x + __ldcg(&g_po[tid]) + __ldcg(&g_po[Dm + tid])
              + __ldcg(&g_po[2 * Dm + tid]) + __ldcg(&g_po[3 * Dm + tid]);
        {
            float yy = ln1024(x, ln2w + l * Dm, ln2b + l * Dm, s_red);
            float sf = s[0 * Dm + tid];
            float mk = fmk[l * Dm + tid], mr = fmr[l * Dm + tid];
            s_v0[tid] = yy * mk + sf * (1.0f - mk);
            s_v1[tid] = yy * mr + sf * (1.0f - mr);
            if (b0) nsl[0 * Dm + tid] = yy;
        }
        __syncthreads();
        for (int t = gw; t < Hm + Dm; t += NWG) {
            bool isk = (t < Hm);
            const float* W = isk ? (fkw + hd + (size_t)t * Dm)
                                 : (frw + dd + (size_t)(t - Hm) * Dm);
            float acc = dot8((const float4*)W, (const float4*)(isk ? s_v0 : s_v1), lane);
            if (lane == 0) {
                if (isk) { float u = fmaxf(acc, 0.0f); __stcg(&g_fk[t], u * u); }
                else     { __stcg(&g_fr[t - Hm], 1.0f / (1.0f + expf(-acc))); }
            }
        }
        pf_l2(fvw + hd, HD);
        gsync(++bar);

        // ---- phase 4: fv partials (K=4096, 4 chunks of 1024) ----
        for (int j = tid; j < Hm; j += NT) s_fk[j] = __ldcg(&g_fk[j]);
        __syncthreads();
        for (int t = gw; t < 4 * Dm; t += NWG) {
            int row = t >> 2, ch = t & 3;
            float acc = dot8((const float4*)(fvw + hd + (size_t)row * Hm + ch * Dm),
                             (const float4*)(s_fk + ch * Dm), lane);
            if (lane == 0) __stcg(&g_pf[ch * Dm + row], acc);
        }
        if (l + 1 < Lm) {
            const size_t dd2 = (size_t)(l + 1) * Dm * Dm;
            pf_l2(kw + dd2, DD); pf_l2(vw + dd2, DD); pf_l2(rw + dd2, DD);
        }
        if (l >= Lm - 4) {   // drip-prefetch head across last 4 layers
            const size_t CH = (size_t)15 * 1024 * 1024;
            pf_l2((const char*)headw + (size_t)(l - (Lm - 4)) * CH, CH);
        }
        gsync(++bar);

        // ---- residual update for next layer ----
        x = x + __ldcg(&g_fr[tid]) * (__ldcg(&g_pf[tid]) + __ldcg(&g_pf[Dm + tid])
              + __ldcg(&g_pf[2 * Dm + tid]) + __ldcg(&g_pf[3 * Dm + tid]));
    }

    // ---- final LN + head matvec (2 rows/warp in flight) ----
    {
        float xf = ln1024(x, lnoutw, lnoutb, s_red);
        s_v0[tid] = xf;
    }
    __syncthreads();
    for (int t = gw; t < Vm; t += 2 * NWG) {
        int t2 = t + NWG;
        const float4* w0 = (const float4*)(headw + (size_t)t * Dm);
        const float4* x4 = (const float4*)s_v0;
        float a0 = 0.f, a1 = 0.f;
        if (t2 < Vm) {
            const float4* w1 = (const float4*)(headw + (size_t)t2 * Dm);
#pragma unroll
            for (int j = 0; j < 8; j++) {
                float4 p = __ldcs(w0 + j * 32 + lane);
                float4 q = __ldcs(w1 + j * 32 + lane);
                float4 c = x4[j * 32 + lane];
                a0 = fmaf(p.x, c.x, fmaf(p.y, c.y, fmaf(p.z, c.z, fmaf(p.w, c.w, a0))));
                a1 = fmaf(q.x, c.x, fmaf(q.y, c.y, fmaf(q.z, c.z, fmaf(q.w, c.w, a1))));
            }
            a0 = warp_sum(a0); a1 = warp_sum(a1);
            if (lane == 0) { logits[t] = a0; logits[t2] = a1; }
        } else {
#pragma unroll
            for (int j = 0; j < 8; j++) {
                float4 p = __ldcs(w0 + j * 32 + lane);
                float4 c = x4[j * 32 + lane];
                a0 = fmaf(p.x, c.x, fmaf(p.y, c.y, fmaf(p.z, c.z, fmaf(p.w, c.w, a0))));
            }
            a0 = warp_sum(a0);
            if (lane == 0) logits[t] = a0;
        }
    }
}

// ---------------- launch ----------------
extern "C" void kernel_launch(void* const* d_in, const int* in_sizes, int n_in,
                              void* d_out, int out_size) {
    const int*   tok    = (const int*)  d_in[0];
    const float* state  = (const float*)d_in[1];
    const float* emb    = (const float*)d_in[2];
    const float* ln0w   = (const float*)d_in[3];
    const float* ln0b   = (const float*)d_in[4];
    const float* ln1w   = (const float*)d_in[5];
    const float* ln1b   = (const float*)d_in[6];
    const float* tmk    = (const float*)d_in[7];
    const float* tmv    = (const float*)d_in[8];
    const float* tmr    = (const float*)d_in[9];
    const float* tf     = (const float*)d_in[10];
    const float* td     = (const float*)d_in[11];
    const float* kw     = (const float*)d_in[12];
    const float* vw     = (const float*)d_in[13];
    const float* rw     = (const float*)d_in[14];
    const float* ow     = (const float*)d_in[15];
    const float* ln2w   = (const float*)d_in[16];
    const float* ln2b   = (const float*)d_in[17];
    const float* fmk    = (const float*)d_in[18];
    const float* fmr    = (const float*)d_in[19];
    const float* fkw    = (const float*)d_in[20];
    const float* fvw    = (const float*)d_in[21];
    const float* frw    = (const float*)d_in[22];
    const float* lnoutw = (const float*)d_in[23];
    const float* lnoutb = (const float*)d_in[24];
    const float* headw  = (const float*)d_in[25];

    float* logits = (float*)d_out;
    float* ns     = (float*)d_out + Vm;

    rwkv_all<<<NB, NT>>>(tok, state, emb, ln0w, ln0b, ln1w, ln1b,
                         tmk, tmv, tmr, tf, td, kw, vw, rw, ow,
                         ln2w, ln2b, fmk, fmr, fkw, fvw, frw,
                         lnoutw, lnoutb, headw, logits, ns);
}

// round 9
// speedup vs baseline: 1.0432x; 1.0432x over previous
#include <cuda_runtime.h>
#include <math.h>
#include <stdint.h>

#define Dm 1024
#define Hm 4096
#define Lm 12
#define Vm 50277
#define NB 148
#define NT 1024
#define NWG (NB * 32)
#define NTH (NB * NT)

// per-block task counts (block-contiguous assignment)
#define T1 (3 * Dm)
#define T2 (4 * Dm)
#define T3 (Hm + Dm)
#define T4 (4 * Dm)
#define NP1 21      // ceil(3072/148)
#define NP2 28      // ceil(4096/148)
#define NP3 35      // ceil(5120/148)
#define NP4 28      // ceil(4096/148)
#define PFB (96 * 1024)          // bytes per smem prefetch buffer
#define CAP3 24                  // PFB/4KB rows coverable
#define CAP4 24

// ---------------- global scratch (allocation-free) ----------------
__device__ float g_k[Dm], g_v[Dm], g_r[Dm];
__device__ float g_po[4 * Dm];
__device__ float g_fk[Hm], g_fr[Dm];
__device__ float g_pf[4 * Dm];

// ---------------- grid barrier (R5 atomic version — proven best) ----------------
__device__ unsigned g_cnt3[3];
__device__ unsigned g_gen;

__device__ __forceinline__ unsigned ld_acq(const unsigned* p) {
    unsigned v;
    asm volatile("ld.acquire.gpu.global.u32 %0, [%1];" : "=r"(v) : "l"(p) : "memory");
    return v;
}
__device__ __forceinline__ unsigned atom_add_rel(unsigned* p, unsigned a) {
    unsigned v;
    asm volatile("atom.release.gpu.global.add.u32 %0, [%1], %2;" : "=r"(v) : "l"(p), "r"(a) : "memory");
    return v;
}
__device__ __forceinline__ void st_rel(unsigned* p, unsigned v) {
    asm volatile("st.release.gpu.global.u32 [%0], %1;" :: "l"(p), "r"(v) : "memory");
}
__device__ __forceinline__ void st_rlx(unsigned* p, unsigned v) {
    asm volatile("st.relaxed.gpu.global.u32 [%0], %1;" :: "l"(p), "r"(v) : "memory");
}

__device__ __forceinline__ void gsync() {
    __syncthreads();
    if (threadIdx.x == 0) {
        unsigned g = ld_acq(&g_gen);
        unsigned old = atom_add_rel(&g_cnt3[g % 3u], 1u);
        if (old == (unsigned)(NB - 1)) {
            st_rlx(&g_cnt3[(g + 2u) % 3u], 0u);
            st_rel(&g_gen, g + 1u);
        } else {
            while (ld_acq(&g_gen) == g) { }
        }
    }
    __syncthreads();
}

// ---------------- cp.async helpers ----------------
__device__ __forceinline__ void cpa16(uint32_t d, const void* s) {
    asm volatile("cp.async.cg.shared.global [%0], [%1], 16;" :: "r"(d), "l"(s));
}
__device__ __forceinline__ void cpa_commit() { asm volatile("cp.async.commit_group;" ::: "memory"); }
__device__ __forceinline__ void cpa_wait1()  { asm volatile("cp.async.wait_group 1;" ::: "memory"); }

// ---------------- L2 prefetch hint (head drip + overflow rows) ----------------
__device__ __forceinline__ void pf_l2(const void* p, size_t bytes) {
    const char* c = (const char*)p;
    size_t start = ((size_t)(blockIdx.x * NT + threadIdx.x)) << 7;
    size_t step  = ((size_t)NTH) << 7;
    for (size_t i = start; i < bytes; i += step)
        asm volatile("prefetch.global.L2 [%0];" :: "l"(c + i));
}

// ---------------- reductions ----------------
__device__ __forceinline__ float warp_sum(float v) {
#pragma unroll
    for (int o = 16; o; o >>= 1) v += __shfl_down_sync(0xffffffffu, v, o);
    return v;
}

__device__ __forceinline__ float block_sum(float v, float* sbuf) {
    int lane = threadIdx.x & 31, wid = threadIdx.x >> 5;
    v = warp_sum(v);
    __syncthreads();
    if (lane == 0) sbuf[wid] = v;
    __syncthreads();
    if (wid == 0) {
        float t = sbuf[lane];
        t = warp_sum(t);
        if (lane == 0) sbuf[0] = t;
    }
    __syncthreads();
    return sbuf[0];
}

__device__ __forceinline__ float ln1024(float v, const float* __restrict__ w,
                                        const float* __restrict__ b, float* sbuf) {
    float mu = block_sum(v, sbuf) * (1.0f / Dm);
    float d = v - mu;
    float var = block_sum(d * d, sbuf) * (1.0f / Dm);
    return d * rsqrtf(var + 1e-5f) * w[threadIdx.x] + b[threadIdx.x];
}

// ---------------- dot helpers ----------------
__device__ __forceinline__ float dot8(const float4* __restrict__ w,
                                      const float4* __restrict__ x, int lane) {
    float acc = 0.f;
#pragma unroll
    for (int j = 0; j < 8; j++) {
        float4 a = __ldcs(w + j * 32 + lane);
        float4 c = x[j * 32 + lane];
        acc = fmaf(a.x, c.x, fmaf(a.y, c.y, fmaf(a.z, c.z, fmaf(a.w, c.w, acc))));
    }
    return warp_sum(acc);
}
__device__ __forceinline__ float dot8s(const float4* w, const float4* x, int lane) {
    float acc = 0.f;
#pragma unroll
    for (int j = 0; j < 8; j++) {
        float4 a = w[j * 32 + lane];
        float4 c = x[j * 32 + lane];
        acc = fmaf(a.x, c.x, fmaf(a.y, c.y, fmaf(a.z, c.z, fmaf(a.w, c.w, acc))));
    }
    return warp_sum(acc);
}
__device__ __forceinline__ float dot2s(const float4* w, const float4* x, int lane) {
    float acc = 0.f;
#pragma unroll
    for (int j = 0; j < 2; j++) {
        float4 a = w[j * 32 + lane];
        float4 c = x[j * 32 + lane];
        acc = fmaf(a.x, c.x, fmaf(a.y, c.y, fmaf(a.z, c.z, fmaf(a.w, c.w, acc))));
    }
    return warp_sum(acc);
}

__device__ __forceinline__ int iclamp(int v, int hi) { return v < 0 ? 0 : (v > hi ? hi : v); }

// prefetch phase-1 rows of a given layer into buffer
__device__ __forceinline__ void prefetch_p1(uint32_t sbuf, const float* kw, const float* vw,
                                            const float* rw, size_t dd, int tid) {
    int base = blockIdx.x * NP1;
    int ntask = iclamp(T1 - base, NP1);
    for (int c = tid; c < ntask * 256; c += NT) {
        int i = c >> 8, off = (c & 255) << 4;
        int g = base + i, mat = g >> 10, row = g & 1023;
        const float* W = (mat == 0) ? kw : (mat == 1) ? vw : rw;
        cpa16(sbuf + c * 16, (const char*)(W + dd + (size_t)row * Dm) + off);
    }
}

// ---------------- the whole network in one persistent kernel ----------------
__global__ __launch_bounds__(NT, 1) void rwkv_all(
    const int* __restrict__ tok, const float* __restrict__ state,
    const float* __restrict__ emb,
    const float* __restrict__ ln0w, const float* __restrict__ ln0b,
    const float* __restrict__ ln1w, const float* __restrict__ ln1b,
    const float* __restrict__ tmk, const float* __restrict__ tmv,
    const float* __restrict__ tmr, const float* __restrict__ tf,
    const float* __restrict__ td,
    const float* __restrict__ kw, const float* __restrict__ vw,
    const float* __restrict__ rw, const float* __restrict__ ow,
    const float* __restrict__ ln2w, const float* __restrict__ ln2b,
    const float* __restrict__ fmk, const float* __restrict__ fmr,
    const float* __restrict__ fkw, const float* __restrict__ fvw,
    const float* __restrict__ frw,
    const float* __restrict__ lnoutw, const float* __restrict__ lnoutb,
    const float* __restrict__ headw,
    float* __restrict__ logits, float* __restrict__ ns)
{
    __shared__ float s_v0[Dm], s_v1[Dm], s_v2[Dm];
    __shared__ float s_fk[Hm];
    __shared__ float s_red[32];
    extern __shared__ char dynbuf[];
    char* bufA = dynbuf;
    char* bufB = dynbuf + PFB;
    const uint32_t sA = (uint32_t)__cvta_generic_to_shared(bufA);
    const uint32_t sB = (uint32_t)__cvta_generic_to_shared(bufB);

    const int tid = threadIdx.x;
    const int wid = tid >> 5, lane = tid & 31;
    const int gw = blockIdx.x * 32 + wid;
    const bool b0 = (blockIdx.x == 0);

    // ---- start streaming layer-0 phase-1 into bufA immediately ----
    prefetch_p1(sA, kw, vw, rw, 0, tid);
    cpa_commit();                                   // 1 group outstanding

    // ---- embed + ln0 (redundant per block) ----
    float x = ln1024(emb[(size_t)(*tok) * Dm + tid], ln0w, ln0b, s_red);

    for (int l = 0; l < Lm; l++) {
        const float* s = state + (size_t)l * 5 * Dm;
        float* nsl = ns + (size_t)l * 5 * Dm;
        const size_t dd = (size_t)l * Dm * Dm;
        const size_t hd = (size_t)l * Hm * Dm;

        const int base1 = blockIdx.x * NP1, ntask1 = iclamp(T1 - base1, NP1);
        const int base2 = blockIdx.x * NP2, ntask2 = iclamp(T2 - base2, NP2);
        const int base3 = blockIdx.x * NP3, ntask3 = iclamp(T3 - base3, NP3);
        const int base4 = blockIdx.x * NP4, ntask4 = iclamp(T4 - base4, NP4);
        const int npref3 = ntask3 < CAP3 ? ntask3 : CAP3;
        const int npref4 = ntask4 < CAP4 ? ntask4 : CAP4;

        // ======== phase 1: LN1 + token-mix, k/v/r dots from bufA ========
        {
            float xx = ln1024(x, ln1w + l * Dm, ln1b + l * Dm, s_red);
            float ss = s[1 * Dm + tid];
            float mk = tmk[l * Dm + tid], mv = tmv[l * Dm + tid], mr = tmr[l * Dm + tid];
            s_v0[tid] = xx * mk + ss * (1.0f - mk);
            s_v1[tid] = xx * mv + ss * (1.0f - mv);
            s_v2[tid] = xx * mr + ss * (1.0f - mr);
            if (b0) nsl[1 * Dm + tid] = xx;
        }
        // issue phase-2 prefetch (ow) into bufB, then wait P1 data
        for (int c = tid; c < ntask2 * 64; c += NT) {
            int i = c >> 6, off = (c & 63) << 4;
            int g = base2 + i, row = g >> 2, ch = g & 3;
            cpa16(sB + c * 16, (const char*)(ow + dd + (size_t)row * Dm + ch * 256) + off);
        }
        cpa_commit();
        cpa_wait1();
        __syncthreads();
        if (wid < ntask1) {
            int g = base1 + wid, mat = g >> 10, row = g & 1023;
            const float* xv = (mat == 0) ? s_v0 : (mat == 1) ? s_v1 : s_v2;
            float acc = dot8s((const float4*)(bufA + (size_t)wid * 4096), (const float4*)xv, lane);
            if (lane == 0) {
                if (mat == 0)      __stcg(&g_k[row], acc);
                else if (mat == 1) __stcg(&g_v[row], acc);
                else               __stcg(&g_r[row], 1.0f / (1.0f + expf(-acc)));
            }
        }
        gsync();

        // ======== phase 2: WKV recurrence + ow dots from bufB ========
        {
            float k = __ldcg(&g_k[tid]), v = __ldcg(&g_v[tid]);
            float aa = s[2 * Dm + tid], bb = s[3 * Dm + tid], pp = s[4 * Dm + tid];
            float ww = tf[l * Dm + tid] + k;
            float p = fmaxf(pp, ww);
            float e1 = expf(pp - p), e2 = expf(ww - p);
            float wkv = (e1 * aa + e2 * v) / (e1 * bb + e2);
            float ww2 = pp + td[l * Dm + tid];
            float p2 = fmaxf(ww2, k);
            float f1 = expf(ww2 - p2), f2 = expf(k - p2);
            s_v0[tid] = __ldcg(&g_r[tid]) * wkv;
            if (b0) {
                nsl[2 * Dm + tid] = f1 * aa + f2 * v;
                nsl[3 * Dm + tid] = f1 * bb + f2;
                nsl[4 * Dm + tid] = p2;
            }
        }
        // issue phase-3 prefetch (fk/fr) into bufA + hints for overflow rows
        for (int c = tid; c < npref3 * 256; c += NT) {
            int i = c >> 8, off = (c & 255) << 4;
            int g = base3 + i;
            const float* W = (g < Hm) ? (fkw + hd + (size_t)g * Dm)
                                      : (frw + dd + (size_t)(g - Hm) * Dm);
            cpa16(sA + c * 16, (const char*)W + off);
        }
        for (int c = tid; c < (ntask3 - npref3) * 32; c += NT) {
            int i = npref3 + (c >> 5), g = base3 + i;
            const char* W = (const char*)((g < Hm) ? (fkw + hd + (size_t)g * Dm)
                                                   : (frw + dd + (size_t)(g - Hm) * Dm));
            asm volatile("prefetch.global.L2 [%0];" :: "l"(W + (size_t)(c & 31) * 128));
        }
        cpa_commit();
        cpa_wait1();
        __syncthreads();
        if (wid < ntask2) {
            int g = base2 + wid, row = g >> 2, ch = g & 3;
            float acc = dot2s((const float4*)(bufB + (size_t)wid * 1024),
                              (const float4*)(s_v0 + ch * 256), lane);
            if (lane == 0) __stcg(&g_po[ch * Dm + row], acc);
        }
        gsync();

        // ======== phase 3: residual + LN2 + FFN mix, fk/fr dots ========
        x = x + __ldcg(&g_po[tid]) + __ldcg(&g_po[Dm + tid])
              + __ldcg(&g_po[2 * Dm + tid]) + __ldcg(&g_po[3 * Dm + tid]);
        {
            float yy = ln1024(x, ln2w + l * Dm, ln2b + l * Dm, s_red);
            float sf = s[0 * Dm + tid];
            float mk = fmk[l * Dm + tid], mr = fmr[l * Dm + tid];
            s_v0[tid] = yy * mk + sf * (1.0f - mk);
            s_v1[tid] = yy * mr + sf * (1.0f - mr);
            if (b0) nsl[0 * Dm + tid] = yy;
        }
        // issue phase-4 prefetch (fv chunks) into bufB + hints for overflow
        for (int c = tid; c < npref4 * 256; c += NT) {
            int i = c >> 8, off = (c & 255) << 4;
            int g = base4 + i, row = g >> 2, ch = g & 3;
            cpa16(sB + c * 16,
                  (const char*)(fvw + hd + (size_t)row * Hm + ch * 1024) + off);
        }
        for (int c = tid; c < (ntask4 - npref4) * 32; c += NT) {
            int i = npref4 + (c >> 5), g = base4 + i, row = g >> 2, ch = g & 3;
            asm volatile("prefetch.global.L2 [%0];"
                         :: "l"((const char*)(fvw + hd + (size_t)row * Hm + ch * 1024)
                                + (size_t)(c & 31) * 128));
        }
        cpa_commit();
        cpa_wait1();
        __syncthreads();
        for (int i = wid; i < ntask3; i += 32) {
            int g = base3 + i;
            bool isk = (g < Hm);
            const float* xv = isk ? s_v0 : s_v1;
            float acc;
            if (i < npref3) {
                acc = dot8s((const float4*)(bufA + (size_t)i * 4096), (const float4*)xv, lane);
            } else {
                const float* W = isk ? (fkw + hd + (size_t)g * Dm)
                                     : (frw + dd + (size_t)(g - Hm) * Dm);
                acc = dot8((const float4*)W, (const float4*)xv, lane);
            }
            if (lane == 0) {
                if (isk) { float u = fmaxf(acc, 0.0f); __stcg(&g_fk[g], u * u); }
                else     { __stcg(&g_fr[g - Hm], 1.0f / (1.0f + expf(-acc))); }
            }
        }
        gsync();

        // ======== phase 4: fv dots from bufB ========
        for (int j = tid; j < Hm; j += NT) s_fk[j] = __ldcg(&g_fk[j]);
        // issue next layer's phase-1 prefetch into bufA; drip head hints late
        if (l + 1 < Lm) {
            prefetch_p1(sA, kw, vw, rw, (size_t)(l + 1) * Dm * Dm, tid);
        }
        if (l >= Lm - 4) {
            const size_t CH = (size_t)15 * 1024 * 1024;
            pf_l2((const char*)headw + (size_t)(l - (Lm - 4)) * CH, CH);
        }
        cpa_commit();
        cpa_wait1();
        __syncthreads();
        if (wid < ntask4) {
            int g = base4 + wid, row = g >> 2, ch = g & 3;
            float acc;
            if (wid < npref4) {
                acc = dot8s((const float4*)(bufB + (size_t)wid * 4096),
                            (const float4*)(s_fk + ch * 1024), lane);
            } else {
                acc = dot8((const float4*)(fvw + hd + (size_t)row * Hm + ch * 1024),
                           (const float4*)(s_fk + ch * 1024), lane);
            }
            if (lane == 0) __stcg(&g_pf[ch * Dm + row], acc);
        }
        gsync();

        // ---- residual update for next layer ----
        x = x + __ldcg(&g_fr[tid]) * (__ldcg(&g_pf[tid]) + __ldcg(&g_pf[Dm + tid])
              + __ldcg(&g_pf[2 * Dm + tid]) + __ldcg(&g_pf[3 * Dm + tid]));
    }

    // ---- final LN + head matvec (2 rows/warp in flight) ----
    {
        float xf = ln1024(x, lnoutw, lnoutb, s_red);
        s_v0[tid] = xf;
    }
    __syncthreads();
    for (int t = gw; t < Vm; t += 2 * NWG) {
        int t2 = t + NWG;
        const float4* w0 = (const float4*)(headw + (size_t)t * Dm);
        const float4* x4 = (const float4*)s_v0;
        float a0 = 0.f, a1 = 0.f;
        if (t2 < Vm) {
            const float4* w1 = (const float4*)(headw + (size_t)t2 * Dm);
#pragma unroll
            for (int j = 0; j < 8; j++) {
                float4 p = __ldcs(w0 + j * 32 + lane);
                float4 q = __ldcs(w1 + j * 32 + lane);
                float4 c = x4[j * 32 + lane];
                a0 = fmaf(p.x, c.x, fmaf(p.y, c.y, fmaf(p.z, c.z, fmaf(p.w, c.w, a0))));
                a1 = fmaf(q.x, c.x, fmaf(q.y, c.y, fmaf(q.z, c.z, fmaf(q.w, c.w, a1))));
            }
            a0 = warp_sum(a0); a1 = warp_sum(a1);
            if (lane == 0) { logits[t] = a0; logits[t2] = a1; }
        } else {
#pragma unroll
            for (int j = 0; j < 8; j++) {
                float4 p = __ldcs(w0 + j * 32 + lane);
                float4 c = x4[j * 32 + lane];
                a0 = fmaf(p.x, c.x, fmaf(p.y, c.y, fmaf(p.z, c.z, fmaf(p.w, c.w, a0))));
            }
            a0 = warp_sum(a0);
            if (lane == 0) logits[t] = a0;
        }
    }
}

// ---------------- launch ----------------
extern "C" void kernel_launch(void* const* d_in, const int* in_sizes, int n_in,
                              void* d_out, int out_size) {
    const int*   tok    = (const int*)  d_in[0];
    const float* state  = (const float*)d_in[1];
    const float* emb    = (const float*)d_in[2];
    const float* ln0w   = (const float*)d_in[3];
    const float* ln0b   = (const float*)d_in[4];
    const float* ln1w   = (const float*)d_in[5];
    const float* ln1b   = (const float*)d_in[6];
    const float* tmk    = (const float*)d_in[7];
    const float* tmv    = (const float*)d_in[8];
    const float* tmr    = (const float*)d_in[9];
    const float* tf     = (const float*)d_in[10];
    const float* td     = (const float*)d_in[11];
    const float* kw     = (const float*)d_in[12];
    const float* vw     = (const float*)d_in[13];
    const float* rw     = (const float*)d_in[14];
    const float* ow     = (const float*)d_in[15];
    const float* ln2w   = (const float*)d_in[16];
    const float* ln2b   = (const float*)d_in[17];
    const float* fmk    = (const float*)d_in[18];
    const float* fmr    = (const float*)d_in[19];
    const float* fkw    = (const float*)d_in[20];
    const float* fvw    = (const float*)d_in[21];
    const float* frw    = (const float*)d_in[22];
    const float* lnoutw = (const float*)d_in[23];
    const float* lnoutb = (const float*)d_in[24];
    const float* headw  = (const float*)d_in[25];

    float* logits = (float*)d_out;
    float* ns     = (float*)d_out + Vm;

    cudaFuncSetAttribute(rwkv_all, cudaFuncAttributeMaxDynamicSharedMemorySize, 2 * PFB);

    rwkv_all<<<NB, NT, 2 * PFB>>>(tok, state, emb, ln0w, ln0b, ln1w, ln1b,
                                  tmk, tmv, tmr, tf, td, kw, vw, rw, ow,
                                  ln2w, ln2b, fmk, fmr, fkw, fvw, frw,
                                  lnoutw, lnoutb, headw, logits, ns);
}